// round 1
// baseline (speedup 1.0000x reference)
#include <cuda_runtime.h>

#define NNODES 10000
#define NEDGES 320000
#define ETOT   (NNODES + NEDGES)
#define CH     256

// ---- scratch (static device allocations; no cudaMalloc allowed) ----
__device__ float g_H[NNODES * CH];        // node linear projection
__device__ float g_AB[NNODES * 2 * CH];   // [A | B] per node (A = W_s1[:, :256] @ h, B = W_s1[:, 256:] @ h)
__device__ float g_AGG[NNODES * CH];      // aggregation buffer (reused across layers)

// ---- packed fp32x2 FMA (Blackwell 2x fp32 pipe; only reachable via PTX) ----
union F2 { float2 f; unsigned long long u; };

__device__ __forceinline__ void fma_x2(F2& d, const F2& a, const F2& b) {
    asm volatile("fma.rn.f32x2 %0, %1, %2, %0;" : "+l"(d.u) : "l"(a.u), "l"(b.u));
}

__device__ __forceinline__ void red_add_v4(float* p, float x, float y, float z, float w) {
    asm volatile("red.global.add.v4.f32 [%0], {%1, %2, %3, %4};"
                 :: "l"(p), "f"(x), "f"(y), "f"(z), "f"(w) : "memory");
}

// ============================================================================
// GEMM: out[M, NOUT] = act(A[M, K]) @ W^T + bias
//   W layout: row-major [NOUT, K] normally.
//   SPLIT mode: W is W_s1 [256, 512]; output col j<256 uses W_s1[j, k] (+b_s1[j]),
//               col j>=256 uses W_s1[j-256, 256+k] (no bias).
//   RELU_IN applies relu to the input matrix on load (previous layer's raw agg).
// Tiling: BM=128, BN=64, BK=16, 256 threads, 8x4 micro-tile per thread,
// inner product via fma.rn.f32x2 (pairs over the M dimension).
// ============================================================================
template<bool RELU_IN, bool SPLIT>
__global__ void __launch_bounds__(256) gemm_kernel(
    const float* __restrict__ A, const float* __restrict__ W,
    const float* __restrict__ bias, float* __restrict__ out,
    int M, int K, int NOUT)
{
    constexpr int BM = 128, BN = 64, BK = 16;
    __shared__ float As[BK][BM + 4];
    __shared__ float Ws[BK][BN];

    const int t  = threadIdx.x;
    const int bm = blockIdx.x * BM;
    const int bn = blockIdx.y * BN;
    const int tm = t >> 4;    // 0..15 -> rows tm*8 .. tm*8+7
    const int tn = t & 15;    // 0..15 -> cols tn*4 .. tn*4+3

    F2 acc[4][4];  // [m-pair][n]
    #pragma unroll
    for (int i = 0; i < 4; i++)
        #pragma unroll
        for (int j = 0; j < 4; j++) { acc[i][j].f.x = 0.f; acc[i][j].f.y = 0.f; }

    for (int k0 = 0; k0 < K; k0 += BK) {
        // --- load A tile (128 rows x 16 k), transposed into As[k][m] ---
        #pragma unroll
        for (int r = 0; r < 2; r++) {
            int idx = t + r * 256;          // 0..511
            int row = idx >> 2;             // 0..127
            int kq  = (idx & 3) << 2;       // 0,4,8,12
            int gm  = bm + row;
            float4 v = make_float4(0.f, 0.f, 0.f, 0.f);
            if (gm < M)
                v = *reinterpret_cast<const float4*>(&A[(size_t)gm * K + k0 + kq]);
            if (RELU_IN) {
                v.x = fmaxf(v.x, 0.f); v.y = fmaxf(v.y, 0.f);
                v.z = fmaxf(v.z, 0.f); v.w = fmaxf(v.w, 0.f);
            }
            As[kq + 0][row] = v.x; As[kq + 1][row] = v.y;
            As[kq + 2][row] = v.z; As[kq + 3][row] = v.w;
        }
        // --- load W tile (64 out-cols x 16 k), transposed into Ws[k][j] ---
        {
            int row = t >> 2;               // 0..63
            int kq  = (t & 3) << 2;
            int j   = bn + row;
            const float* wp;
            if (SPLIT)
                wp = (j < CH) ? (W + (size_t)j * (2 * CH) + k0 + kq)
                              : (W + (size_t)(j - CH) * (2 * CH) + CH + k0 + kq);
            else
                wp = W + (size_t)j * K + k0 + kq;
            float4 v = *reinterpret_cast<const float4*>(wp);
            Ws[kq + 0][row] = v.x; Ws[kq + 1][row] = v.y;
            Ws[kq + 2][row] = v.z; Ws[kq + 3][row] = v.w;
        }
        __syncthreads();

        #pragma unroll
        for (int k = 0; k < BK; k++) {
            F2 a[4];
            const float2* ap = reinterpret_cast<const float2*>(&As[k][tm * 8]);
            a[0].f = ap[0]; a[1].f = ap[1]; a[2].f = ap[2]; a[3].f = ap[3];
            float4 w = *reinterpret_cast<const float4*>(&Ws[k][tn * 4]);
            F2 wb[4];
            wb[0].f = make_float2(w.x, w.x);
            wb[1].f = make_float2(w.y, w.y);
            wb[2].f = make_float2(w.z, w.z);
            wb[3].f = make_float2(w.w, w.w);
            #pragma unroll
            for (int i = 0; i < 4; i++)
                #pragma unroll
                for (int j = 0; j < 4; j++)
                    fma_x2(acc[i][j], a[i], wb[j]);
        }
        __syncthreads();
    }

    // --- epilogue: +bias, float4 stores ---
    float4 bv;
    {
        int gj = bn + tn * 4;
        if (SPLIT) {
            bv.x = (gj + 0 < CH) ? bias[gj + 0] : 0.f;
            bv.y = (gj + 1 < CH) ? bias[gj + 1] : 0.f;
            bv.z = (gj + 2 < CH) ? bias[gj + 2] : 0.f;
            bv.w = (gj + 3 < CH) ? bias[gj + 3] : 0.f;
        } else {
            bv = *reinterpret_cast<const float4*>(&bias[gj]);
        }
    }
    #pragma unroll
    for (int r = 0; r < 8; r++) {
        int gm = bm + tm * 8 + r;
        if (gm >= M) continue;
        int i = r >> 1;
        float4 o;
        if ((r & 1) == 0) {
            o.x = acc[i][0].f.x + bv.x; o.y = acc[i][1].f.x + bv.y;
            o.z = acc[i][2].f.x + bv.z; o.w = acc[i][3].f.x + bv.w;
        } else {
            o.x = acc[i][0].f.y + bv.x; o.y = acc[i][1].f.y + bv.y;
            o.z = acc[i][2].f.y + bv.z; o.w = acc[i][3].f.y + bv.w;
        }
        *reinterpret_cast<float4*>(&out[(size_t)gm * NOUT + bn + tn * 4]) = o;
    }
}

// ============================================================================
// Edge kernel: one warp per edge (grid-stride).
//   score_e = sigmoid( sum_c relu(A[dst,c] + B[src,c]) * w2[c] + b2 )
//   agg[dst, :] += score_e * H[src, :]   (red.global.add.v4.f32)
// Self-loops (e >= NEDGES): src = dst = e - NEDGES.
// Lane l owns channels [8l, 8l+8).
// ============================================================================
__global__ void __launch_bounds__(256) edge_kernel(
    const int* __restrict__ edge_index,
    const float* __restrict__ AB, const float* __restrict__ H,
    const float* __restrict__ w2, const float* __restrict__ b2,
    float* __restrict__ agg)
{
    const int lane   = threadIdx.x & 31;
    const int warp0  = (blockIdx.x * (blockDim.x >> 5)) + (threadIdx.x >> 5);
    const int nwarps = gridDim.x * (blockDim.x >> 5);

    const float4 w0 = *reinterpret_cast<const float4*>(&w2[lane * 8]);
    const float4 w1 = *reinterpret_cast<const float4*>(&w2[lane * 8 + 4]);
    const float  bb = b2[0];

    for (int e = warp0; e < ETOT; e += nwarps) {
        int s, d;
        if (e < NEDGES) { s = edge_index[e]; d = edge_index[NEDGES + e]; }
        else            { s = e - NEDGES; d = s; }

        const float4* ad = reinterpret_cast<const float4*>(&AB[(size_t)d * (2 * CH) + lane * 8]);
        const float4* bs = reinterpret_cast<const float4*>(&AB[(size_t)s * (2 * CH) + CH + lane * 8]);
        float4 a0 = ad[0], a1 = ad[1];
        float4 b0 = bs[0], b1 = bs[1];

        float p;
        p  = fmaxf(a0.x + b0.x, 0.f) * w0.x;
        p += fmaxf(a0.y + b0.y, 0.f) * w0.y;
        p += fmaxf(a0.z + b0.z, 0.f) * w0.z;
        p += fmaxf(a0.w + b0.w, 0.f) * w0.w;
        p += fmaxf(a1.x + b1.x, 0.f) * w1.x;
        p += fmaxf(a1.y + b1.y, 0.f) * w1.y;
        p += fmaxf(a1.z + b1.z, 0.f) * w1.z;
        p += fmaxf(a1.w + b1.w, 0.f) * w1.w;

        #pragma unroll
        for (int off = 16; off > 0; off >>= 1)
            p += __shfl_xor_sync(0xffffffffu, p, off);

        float score = 1.f / (1.f + __expf(-(p + bb)));

        const float4* hs = reinterpret_cast<const float4*>(&H[(size_t)s * CH + lane * 8]);
        float4 h0 = hs[0], h1 = hs[1];

        float* outp = &agg[(size_t)d * CH + lane * 8];
        red_add_v4(outp,     score * h0.x, score * h0.y, score * h0.z, score * h0.w);
        red_add_v4(outp + 4, score * h1.x, score * h1.y, score * h1.z, score * h1.w);
    }
}

__global__ void __launch_bounds__(256) zero_kernel(float* __restrict__ p, int n4) {
    int i = blockIdx.x * blockDim.x + threadIdx.x;
    if (i < n4) reinterpret_cast<float4*>(p)[i] = make_float4(0.f, 0.f, 0.f, 0.f);
}

extern "C" void kernel_launch(void* const* d_in, const int* in_sizes, int n_in,
                              void* d_out, int out_size)
{
    (void)in_sizes; (void)n_in;
    const float* x  = (const float*)d_in[0];
    const int*   ei = (const int*)d_in[1];
    const float* W_lin[3] = {(const float*)d_in[2],  (const float*)d_in[8],  (const float*)d_in[14]};
    const float* b_lin[3] = {(const float*)d_in[3],  (const float*)d_in[9],  (const float*)d_in[15]};
    const float* W_s1[3]  = {(const float*)d_in[4],  (const float*)d_in[10], (const float*)d_in[16]};
    const float* b_s1[3]  = {(const float*)d_in[5],  (const float*)d_in[11], (const float*)d_in[17]};
    const float* W_s2[3]  = {(const float*)d_in[6],  (const float*)d_in[12], (const float*)d_in[18]};
    const float* b_s2[3]  = {(const float*)d_in[7],  (const float*)d_in[13], (const float*)d_in[19]};

    float *H, *AB, *AGG;
    cudaGetSymbolAddress((void**)&H,   g_H);
    cudaGetSymbolAddress((void**)&AB,  g_AB);
    cudaGetSymbolAddress((void**)&AGG, g_AGG);
    float* out = (float*)d_out;
    (void)out_size;

    const dim3 blk(256);
    const dim3 gH((NNODES + 127) / 128, CH / 64);
    const dim3 gAB((NNODES + 127) / 128, (2 * CH) / 64);
    const int  zgrid = (NNODES * CH / 4 + 255) / 256;
    const int  egrid = 2048;

    // ---- layer 1 (input: x [N,64], no input relu) ----
    gemm_kernel<false, false><<<gH,  blk>>>(x,   W_lin[0], b_lin[0], H,  NNODES, 64, CH);
    gemm_kernel<false, true ><<<gAB, blk>>>(H,   W_s1[0],  b_s1[0],  AB, NNODES, CH, 2 * CH);
    zero_kernel<<<zgrid, blk>>>(AGG, NNODES * CH / 4);
    edge_kernel<<<egrid, blk>>>(ei, AB, H, W_s2[0], b_s2[0], AGG);

    // ---- layer 2 (input: relu(AGG)) ----
    gemm_kernel<true,  false><<<gH,  blk>>>(AGG, W_lin[1], b_lin[1], H,  NNODES, CH, CH);
    gemm_kernel<false, true ><<<gAB, blk>>>(H,   W_s1[1],  b_s1[1],  AB, NNODES, CH, 2 * CH);
    zero_kernel<<<zgrid, blk>>>(AGG, NNODES * CH / 4);
    edge_kernel<<<egrid, blk>>>(ei, AB, H, W_s2[1], b_s2[1], AGG);

    // ---- layer 3 (input: relu(AGG), output raw to d_out) ----
    gemm_kernel<true,  false><<<gH,  blk>>>(AGG, W_lin[2], b_lin[2], H,  NNODES, CH, CH);
    gemm_kernel<false, true ><<<gAB, blk>>>(H,   W_s1[2],  b_s1[2],  AB, NNODES, CH, 2 * CH);
    zero_kernel<<<zgrid, blk>>>(out, NNODES * CH / 4);
    edge_kernel<<<egrid, blk>>>(ei, AB, H, W_s2[2], b_s2[2], out);
}

// round 2
// speedup vs baseline: 1.3792x; 1.3792x over previous
#include <cuda_runtime.h>
#include <cuda_fp16.h>

#define NNODES 10000
#define NEDGES 320000
#define ETOT   (NNODES + NEDGES)
#define CH     256

// ---- scratch (static device allocations; no cudaMalloc allowed) ----
__device__ __align__(16) float  g_H[NNODES * CH];          // node linear projection (fp32)
__device__ __align__(16) __half g_AB[NNODES * 2 * CH];     // [A | B] per node, fp16
__device__ __align__(16) float  g_AGG[NNODES * CH];        // aggregation buffer
__device__ int g_rowptr[NNODES + 1];
__device__ int g_cnt[NNODES];
__device__ int g_col[NEDGES];

// ---- packed fp32x2 FMA (Blackwell 2x fp32 pipe; only reachable via PTX) ----
union F2 { float2 f; unsigned long long u; };

__device__ __forceinline__ void fma_x2(F2& d, const F2& a, const F2& b) {
    asm volatile("fma.rn.f32x2 %0, %1, %2, %0;" : "+l"(d.u) : "l"(a.u), "l"(b.u));
}

// ============================================================================
// GEMM: out[M, NOUT] = act(A[M, K]) @ W^T + bias
//   SPLIT: W is W_s1 [256, 512]; out col j<256 uses W_s1[j, :256] (+b_s1[j]),
//          col j>=256 uses W_s1[j-256, 256:] (no bias).
//   RELU_IN applies relu to the input on load. HALF_OUT stores fp16.
// ============================================================================
template<bool RELU_IN, bool SPLIT, bool HALF_OUT>
__global__ void __launch_bounds__(256) gemm_kernel(
    const float* __restrict__ A, const float* __restrict__ W,
    const float* __restrict__ bias, void* __restrict__ out_raw,
    int M, int K, int NOUT)
{
    constexpr int BM = 128, BN = 64, BK = 16;
    __shared__ float As[BK][BM + 4];
    __shared__ float Ws[BK][BN];

    const int t  = threadIdx.x;
    const int bm = blockIdx.x * BM;
    const int bn = blockIdx.y * BN;
    const int tm = t >> 4;
    const int tn = t & 15;

    F2 acc[4][4];
    #pragma unroll
    for (int i = 0; i < 4; i++)
        #pragma unroll
        for (int j = 0; j < 4; j++) { acc[i][j].f.x = 0.f; acc[i][j].f.y = 0.f; }

    for (int k0 = 0; k0 < K; k0 += BK) {
        #pragma unroll
        for (int r = 0; r < 2; r++) {
            int idx = t + r * 256;
            int row = idx >> 2;
            int kq  = (idx & 3) << 2;
            int gm  = bm + row;
            float4 v = make_float4(0.f, 0.f, 0.f, 0.f);
            if (gm < M)
                v = *reinterpret_cast<const float4*>(&A[(size_t)gm * K + k0 + kq]);
            if (RELU_IN) {
                v.x = fmaxf(v.x, 0.f); v.y = fmaxf(v.y, 0.f);
                v.z = fmaxf(v.z, 0.f); v.w = fmaxf(v.w, 0.f);
            }
            As[kq + 0][row] = v.x; As[kq + 1][row] = v.y;
            As[kq + 2][row] = v.z; As[kq + 3][row] = v.w;
        }
        {
            int row = t >> 2;
            int kq  = (t & 3) << 2;
            int j   = bn + row;
            const float* wp;
            if (SPLIT)
                wp = (j < CH) ? (W + (size_t)j * (2 * CH) + k0 + kq)
                              : (W + (size_t)(j - CH) * (2 * CH) + CH + k0 + kq);
            else
                wp = W + (size_t)j * K + k0 + kq;
            float4 v = *reinterpret_cast<const float4*>(wp);
            Ws[kq + 0][row] = v.x; Ws[kq + 1][row] = v.y;
            Ws[kq + 2][row] = v.z; Ws[kq + 3][row] = v.w;
        }
        __syncthreads();

        #pragma unroll
        for (int k = 0; k < BK; k++) {
            F2 a[4];
            const float2* ap = reinterpret_cast<const float2*>(&As[k][tm * 8]);
            a[0].f = ap[0]; a[1].f = ap[1]; a[2].f = ap[2]; a[3].f = ap[3];
            float4 w = *reinterpret_cast<const float4*>(&Ws[k][tn * 4]);
            F2 wb[4];
            wb[0].f = make_float2(w.x, w.x);
            wb[1].f = make_float2(w.y, w.y);
            wb[2].f = make_float2(w.z, w.z);
            wb[3].f = make_float2(w.w, w.w);
            #pragma unroll
            for (int i = 0; i < 4; i++)
                #pragma unroll
                for (int j = 0; j < 4; j++)
                    fma_x2(acc[i][j], a[i], wb[j]);
        }
        __syncthreads();
    }

    float4 bv;
    {
        int gj = bn + tn * 4;
        if (SPLIT) {
            bv.x = (gj + 0 < CH) ? bias[gj + 0] : 0.f;
            bv.y = (gj + 1 < CH) ? bias[gj + 1] : 0.f;
            bv.z = (gj + 2 < CH) ? bias[gj + 2] : 0.f;
            bv.w = (gj + 3 < CH) ? bias[gj + 3] : 0.f;
        } else {
            bv = *reinterpret_cast<const float4*>(&bias[gj]);
        }
    }
    #pragma unroll
    for (int r = 0; r < 8; r++) {
        int gm = bm + tm * 8 + r;
        if (gm >= M) continue;
        int i = r >> 1;
        float4 o;
        if ((r & 1) == 0) {
            o.x = acc[i][0].f.x + bv.x; o.y = acc[i][1].f.x + bv.y;
            o.z = acc[i][2].f.x + bv.z; o.w = acc[i][3].f.x + bv.w;
        } else {
            o.x = acc[i][0].f.y + bv.x; o.y = acc[i][1].f.y + bv.y;
            o.z = acc[i][2].f.y + bv.z; o.w = acc[i][3].f.y + bv.w;
        }
        size_t idx = (size_t)gm * NOUT + bn + tn * 4;
        if (HALF_OUT) {
            __half2 p0 = __floats2half2_rn(o.x, o.y);
            __half2 p1 = __floats2half2_rn(o.z, o.w);
            uint2 pk;
            pk.x = *reinterpret_cast<unsigned*>(&p0);
            pk.y = *reinterpret_cast<unsigned*>(&p1);
            *reinterpret_cast<uint2*>(reinterpret_cast<__half*>(out_raw) + idx) = pk;
        } else {
            *reinterpret_cast<float4*>(reinterpret_cast<float*>(out_raw) + idx) = o;
        }
    }
}

// ============================================================================
// CSR build (per launch; atomics give nondeterministic within-row order,
// which only perturbs fp32 accumulation order — ~1ulp, fine vs 1e-3 gate)
// ============================================================================
__global__ void zero_cnt_kernel() {
    int i = blockIdx.x * blockDim.x + threadIdx.x;
    if (i < NNODES) g_cnt[i] = 0;
}

__global__ void hist_kernel(const int* __restrict__ ei) {
    int e = blockIdx.x * blockDim.x + threadIdx.x;
    if (e < NEDGES) atomicAdd(&g_cnt[ei[NEDGES + e]], 1);
}

__global__ void scan_kernel() {  // single block, 1024 threads
    __shared__ int sh[1024];
    __shared__ int carry_s;
    if (threadIdx.x == 0) carry_s = 0;
    __syncthreads();
    for (int base = 0; base < NNODES; base += 1024) {
        int i = base + (int)threadIdx.x;
        int v = (i < NNODES) ? g_cnt[i] : 0;
        sh[threadIdx.x] = v;
        __syncthreads();
        #pragma unroll
        for (int off = 1; off < 1024; off <<= 1) {
            int tv = (threadIdx.x >= off) ? sh[threadIdx.x - off] : 0;
            __syncthreads();
            sh[threadIdx.x] += tv;
            __syncthreads();
        }
        int carry = carry_s;
        int incl = sh[threadIdx.x];
        if (i < NNODES) {
            g_rowptr[i] = carry + incl - v;  // exclusive prefix
            g_cnt[i] = 0;                    // re-zero for scatter pass
        }
        int c_new = carry + sh[1023];
        __syncthreads();
        if (threadIdx.x == 0) carry_s = c_new;
        __syncthreads();
    }
    if (threadIdx.x == 0) g_rowptr[NNODES] = carry_s;
}

__global__ void scatter_kernel(const int* __restrict__ ei) {
    int e = blockIdx.x * blockDim.x + threadIdx.x;
    if (e < NEDGES) {
        int s = ei[e];
        int d = ei[NEDGES + e];
        int pos = g_rowptr[d] + atomicAdd(&g_cnt[d], 1);
        g_col[pos] = s;
    }
}

// ============================================================================
// Fused score + aggregate kernel: one warp per dst node.
//   A[d] held in registers (fp16), loop over CSR row (self-loop first):
//     score = sigmoid( sum_c relu(A[d,c]+B[s,c]) * w2[c] + b2 )
//     acc  += score * H[s]
//   write agg[d] once. No atomics, no zero pass.
// Lane l owns channels [8l, 8l+8).
// ============================================================================
__global__ void __launch_bounds__(256) agg_kernel(
    const __half* __restrict__ AB, const float* __restrict__ H,
    const float* __restrict__ w2, const float* __restrict__ b2,
    float* __restrict__ agg)
{
    const int lane = threadIdx.x & 31;
    const int d    = blockIdx.x * (blockDim.x >> 5) + (threadIdx.x >> 5);
    if (d >= NNODES) return;

    const float4 w0 = *reinterpret_cast<const float4*>(&w2[lane * 8]);
    const float4 w1 = *reinterpret_cast<const float4*>(&w2[lane * 8 + 4]);
    const float  bb = b2[0];

    // A[d] : 8 halves for my channels
    uint4 araw = *reinterpret_cast<const uint4*>(&AB[(size_t)d * (2 * CH) + lane * 8]);
    float2 a0 = __half22float2(*reinterpret_cast<__half2*>(&araw.x));
    float2 a1 = __half22float2(*reinterpret_cast<__half2*>(&araw.y));
    float2 a2 = __half22float2(*reinterpret_cast<__half2*>(&araw.z));
    float2 a3 = __half22float2(*reinterpret_cast<__half2*>(&araw.w));

    float acc0 = 0.f, acc1 = 0.f, acc2 = 0.f, acc3 = 0.f;
    float acc4 = 0.f, acc5 = 0.f, acc6 = 0.f, acc7 = 0.f;

    const int beg = g_rowptr[d];
    const int end = g_rowptr[d + 1];

    // i == beg-1 encodes the self-loop (s = d)
    for (int i = beg - 1; i < end; ++i) {
        int s = (i < beg) ? d : g_col[i];

        // issue both gathers up front (independent of score)
        uint4 braw = *reinterpret_cast<const uint4*>(&AB[(size_t)s * (2 * CH) + CH + lane * 8]);
        const float4* hp = reinterpret_cast<const float4*>(&H[(size_t)s * CH + lane * 8]);
        float4 h0 = hp[0], h1 = hp[1];

        float2 b0 = __half22float2(*reinterpret_cast<__half2*>(&braw.x));
        float2 b1 = __half22float2(*reinterpret_cast<__half2*>(&braw.y));
        float2 b2v = __half22float2(*reinterpret_cast<__half2*>(&braw.z));
        float2 b3 = __half22float2(*reinterpret_cast<__half2*>(&braw.w));

        float p;
        p  = fmaxf(a0.x + b0.x, 0.f) * w0.x;
        p += fmaxf(a0.y + b0.y, 0.f) * w0.y;
        p += fmaxf(a1.x + b1.x, 0.f) * w0.z;
        p += fmaxf(a1.y + b1.y, 0.f) * w0.w;
        p += fmaxf(a2.x + b2v.x, 0.f) * w1.x;
        p += fmaxf(a2.y + b2v.y, 0.f) * w1.y;
        p += fmaxf(a3.x + b3.x, 0.f) * w1.z;
        p += fmaxf(a3.y + b3.y, 0.f) * w1.w;

        #pragma unroll
        for (int off = 16; off > 0; off >>= 1)
            p += __shfl_xor_sync(0xffffffffu, p, off);

        float score = 1.f / (1.f + __expf(-(p + bb)));

        acc0 = fmaf(score, h0.x, acc0);
        acc1 = fmaf(score, h0.y, acc1);
        acc2 = fmaf(score, h0.z, acc2);
        acc3 = fmaf(score, h0.w, acc3);
        acc4 = fmaf(score, h1.x, acc4);
        acc5 = fmaf(score, h1.y, acc5);
        acc6 = fmaf(score, h1.z, acc6);
        acc7 = fmaf(score, h1.w, acc7);
    }

    float* op = &agg[(size_t)d * CH + lane * 8];
    *reinterpret_cast<float4*>(op)     = make_float4(acc0, acc1, acc2, acc3);
    *reinterpret_cast<float4*>(op + 4) = make_float4(acc4, acc5, acc6, acc7);
}

extern "C" void kernel_launch(void* const* d_in, const int* in_sizes, int n_in,
                              void* d_out, int out_size)
{
    (void)in_sizes; (void)n_in; (void)out_size;
    const float* x  = (const float*)d_in[0];
    const int*   ei = (const int*)d_in[1];
    const float* W_lin[3] = {(const float*)d_in[2],  (const float*)d_in[8],  (const float*)d_in[14]};
    const float* b_lin[3] = {(const float*)d_in[3],  (const float*)d_in[9],  (const float*)d_in[15]};
    const float* W_s1[3]  = {(const float*)d_in[4],  (const float*)d_in[10], (const float*)d_in[16]};
    const float* b_s1[3]  = {(const float*)d_in[5],  (const float*)d_in[11], (const float*)d_in[17]};
    const float* W_s2[3]  = {(const float*)d_in[6],  (const float*)d_in[12], (const float*)d_in[18]};
    const float* b_s2[3]  = {(const float*)d_in[7],  (const float*)d_in[13], (const float*)d_in[19]};

    float *H, *AGG;
    __half* AB;
    cudaGetSymbolAddress((void**)&H,   g_H);
    cudaGetSymbolAddress((void**)&AB,  g_AB);
    cudaGetSymbolAddress((void**)&AGG, g_AGG);
    float* out = (float*)d_out;

    const dim3 blk(256);
    const dim3 gH((NNODES + 127) / 128, CH / 64);
    const dim3 gAB((NNODES + 127) / 128, (2 * CH) / 64);
    const int  agrid = (NNODES + 7) / 8;   // 8 warps per block

    // ---- CSR build (dst-keyed), once per launch ----
    zero_cnt_kernel<<<(NNODES + 255) / 256, blk>>>();
    hist_kernel<<<(NEDGES + 255) / 256, blk>>>(ei);
    scan_kernel<<<1, 1024>>>();
    scatter_kernel<<<(NEDGES + 255) / 256, blk>>>(ei);

    // ---- layer 1 ----
    gemm_kernel<false, false, false><<<gH,  blk>>>(x,   W_lin[0], b_lin[0], H,  NNODES, 64, CH);
    gemm_kernel<false, true,  true ><<<gAB, blk>>>(H,   W_s1[0],  b_s1[0],  AB, NNODES, CH, 2 * CH);
    agg_kernel<<<agrid, blk>>>(AB, H, W_s2[0], b_s2[0], AGG);

    // ---- layer 2 ----
    gemm_kernel<true,  false, false><<<gH,  blk>>>(AGG, W_lin[1], b_lin[1], H,  NNODES, CH, CH);
    gemm_kernel<false, true,  true ><<<gAB, blk>>>(H,   W_s1[1],  b_s1[1],  AB, NNODES, CH, 2 * CH);
    agg_kernel<<<agrid, blk>>>(AB, H, W_s2[1], b_s2[1], AGG);

    // ---- layer 3 (writes d_out directly) ----
    gemm_kernel<true,  false, false><<<gH,  blk>>>(AGG, W_lin[2], b_lin[2], H,  NNODES, CH, CH);
    gemm_kernel<false, true,  true ><<<gAB, blk>>>(H,   W_s1[2],  b_s1[2],  AB, NNODES, CH, 2 * CH);
    agg_kernel<<<agrid, blk>>>(AB, H, W_s2[2], b_s2[2], out);
}